// round 6
// baseline (speedup 1.0000x reference)
#include <cuda_runtime.h>
#include <cuda_bf16.h>
#include <cstdint>

#define HEAD   64
#define SEQ    4096
#define BATCH  4
#define SCALE  0.125f
#define QROWS  128
#define NQT    (SEQ / QROWS)     // 32
#define KTILE  64
#define CHUNK  8                 // kv tiles per CTA chunk
#define MAXCH  8
#define SPITCH 72                // smem row pitch in bf16 (144 B)

// ---------------------------------------------------------------------------
// Scratch
// ---------------------------------------------------------------------------
__device__ __align__(16) __nv_bfloat16 g_qhi [BATCH * SEQ * HEAD];  // [b][t][c] pre-scaled
__device__ __align__(16) __nv_bfloat16 g_qlo [BATCH * SEQ * HEAD];
__device__ __align__(16) __nv_bfloat16 g_khi [BATCH * SEQ * HEAD];  // [b][t][c]
__device__ __align__(16) __nv_bfloat16 g_klo [BATCH * SEQ * HEAD];
__device__ __align__(16) __nv_bfloat16 g_vThi[BATCH * HEAD * SEQ];  // [b][c][t]
__device__ __align__(16) __nv_bfloat16 g_vTlo[BATCH * HEAD * SEQ];
__device__ __align__(16) float g_Opart[BATCH * NQT * MAXCH * QROWS * HEAD];
__device__ __align__(16) float g_lpart[BATCH * NQT * MAXCH * QROWS];

// ---------------------------------------------------------------------------
// PTX helpers (generic sm_80+ features only — target is plain sm_103!)
// ---------------------------------------------------------------------------
__device__ __forceinline__ uint32_t smem_u32(const void* p) {
    uint32_t a;
    asm("{ .reg .u64 t; cvta.to.shared.u64 t, %1; cvt.u32.u64 %0, t; }"
        : "=r"(a) : "l"(p));
    return a;
}

#define LDSM4(r, addr) \
    asm volatile("ldmatrix.sync.aligned.m8n8.x4.shared.b16 {%0,%1,%2,%3}, [%4];" \
        : "=r"((r)[0]), "=r"((r)[1]), "=r"((r)[2]), "=r"((r)[3]) : "r"(addr))

#define MMA16816(d, a, b0, b1) \
    asm volatile("mma.sync.aligned.m16n8k16.row.col.f32.bf16.bf16.f32 " \
        "{%0,%1,%2,%3}, {%4,%5,%6,%7}, {%8,%9}, {%0,%1,%2,%3};" \
        : "+f"((d)[0]), "+f"((d)[1]), "+f"((d)[2]), "+f"((d)[3]) \
        : "r"((a)[0]), "r"((a)[1]), "r"((a)[2]), "r"((a)[3]), "r"(b0), "r"(b1))

__device__ __forceinline__ uint32_t pack_bf2(float a, float b) {
    __nv_bfloat162 h = __floats2bfloat162_rn(a, b);
    return *(uint32_t*)&h;
}

// ---------------------------------------------------------------------------
// Kernel 1: QKV projection -> bf16 hi/lo splits.
// grid = (BATCH*SEQ/128, 3 matrices), 256 threads.
// Thread tile: 4 rows x 8 outputs. float4 smem reads (pitch 68, 16B-aligned).
// ---------------------------------------------------------------------------
__global__ __launch_bounds__(256) void qkv_proj_kernel(
    const float* __restrict__ x,  const float* __restrict__ Wk,
    const float* __restrict__ Wq, const float* __restrict__ Wv)
{
    __shared__ __align__(16) float xs[128][68];
    __shared__ __align__(16) float ws[64][68];

    const int tid  = threadIdx.x;
    const int row0 = blockIdx.x * 128;
    const int m    = blockIdx.y;

    const float* W = (m == 0) ? Wq : (m == 1) ? Wk : Wv;

    // cooperative float4 loads (rows 16B-aligned: pitch 68 floats = 272 B)
    for (int i = tid; i < 128 * 16; i += 256) {
        int r = i >> 4, c4 = (i & 15) << 2;
        *(float4*)&xs[r][c4] = *(const float4*)&x[(size_t)(row0 + r) * HEAD + c4];
    }
    for (int i = tid; i < 64 * 16; i += 256) {
        int r = i >> 4, c4 = (i & 15) << 2;
        *(float4*)&ws[r][c4] = *(const float4*)&W[r * HEAD + c4];
    }
    __syncthreads();

    const int oo = tid & 7;          // output group: cols 8*oo..+7
    const int rr = tid >> 3;         // row group: rows 4*rr..+3
    const int ob = oo * 8;
    const int rb = rr * 4;

    float acc[4][8];
    #pragma unroll
    for (int j = 0; j < 4; j++)
        #pragma unroll
        for (int k = 0; k < 8; k++) acc[j][k] = 0.f;

    #pragma unroll 4
    for (int c4 = 0; c4 < 64; c4 += 4) {
        float4 xv[4], wv[8];
        #pragma unroll
        for (int j = 0; j < 4; j++) xv[j] = *(float4*)&xs[rb + j][c4];
        #pragma unroll
        for (int k = 0; k < 8; k++) wv[k] = *(float4*)&ws[ob + k][c4];
        #pragma unroll
        for (int j = 0; j < 4; j++)
            #pragma unroll
            for (int k = 0; k < 8; k++) {
                acc[j][k] += xv[j].x * wv[k].x;
                acc[j][k] += xv[j].y * wv[k].y;
                acc[j][k] += xv[j].z * wv[k].z;
                acc[j][k] += xv[j].w * wv[k].w;
            }
    }

    const int b  = row0 / SEQ;
    const int tb = (row0 % SEQ) + rb;
    const float sc = (m == 0) ? SCALE : 1.0f;

    #pragma unroll
    for (int j = 0; j < 4; j++) {
        __nv_bfloat16 hi[8], lo[8];
        #pragma unroll
        for (int k = 0; k < 8; k++) {
            float v = acc[j][k] * sc;
            hi[k] = __float2bfloat16(v);
            lo[k] = __float2bfloat16(v - __bfloat162float(hi[k]));
        }
        if (m < 2) {
            size_t ofs = ((size_t)b * SEQ + tb + j) * HEAD + ob;
            __nv_bfloat16* dh = (m == 0 ? g_qhi : g_khi) + ofs;
            __nv_bfloat16* dl = (m == 0 ? g_qlo : g_klo) + ofs;
            uint32_t ph[4], pl[4];
            #pragma unroll
            for (int k = 0; k < 4; k++) {
                __nv_bfloat162 h2; h2.x = hi[2*k]; h2.y = hi[2*k+1];
                __nv_bfloat162 l2; l2.x = lo[2*k]; l2.y = lo[2*k+1];
                ph[k] = *(uint32_t*)&h2;
                pl[k] = *(uint32_t*)&l2;
            }
            *(uint4*)dh = make_uint4(ph[0], ph[1], ph[2], ph[3]);
            *(uint4*)dl = make_uint4(pl[0], pl[1], pl[2], pl[3]);
        } else {
            #pragma unroll
            for (int k = 0; k < 8; k++) {
                size_t ofs = ((size_t)b * HEAD + (ob + k)) * SEQ + tb + j;
                g_vThi[ofs] = hi[k];
                g_vTlo[ofs] = lo[k];
            }
        }
    }
}

// ---------------------------------------------------------------------------
// Kernel 2: FA2-style mma.sync bf16 causal attention (hi/lo split, no max).
// CTA = (b, 128-row q tile, kv chunk of <=8 64-wide kv tiles), 256 threads.
// __launch_bounds__(256,2): occupancy-2 is load-bearing (R5 regression proof).
// ---------------------------------------------------------------------------
__global__ __launch_bounds__(256, 2) void attn_kernel()
{
    __shared__ __align__(16) __nv_bfloat16 sm[4 * 64 * SPITCH];

    const int tid  = threadIdx.x;
    const int w    = tid >> 5;
    const int lane = tid & 31;

    const int bx = blockIdx.x;
    const int b  = bx & 3;
    const int qt = (NQT - 1) - ((bx >> 2) & 31);  // heavy tiles first
    const int ch = bx >> 7;

    const int ntiles = 2 * qt + 2;
    const int t0 = ch * CHUNK;
    const int t1 = (t0 + CHUNK < ntiles) ? (t0 + CHUNK) : ntiles;
    if (t0 >= t1) return;

    const uint32_t smb = smem_u32(sm);
    uint8_t* smB = (uint8_t*)sm;

    // ---- stage Q hi (bytes [0,18432)) and Q lo (bytes [18432,36864)) ----
    {
        const __nv_bfloat16* qh = g_qhi + ((size_t)b * SEQ + (size_t)qt * QROWS) * HEAD;
        const __nv_bfloat16* ql = g_qlo + ((size_t)b * SEQ + (size_t)qt * QROWS) * HEAD;
        for (int i = tid; i < 128 * 8; i += 256) {
            int r = i >> 3, c = i & 7;
            *(uint4*)(smB + r * 144 + c * 16)         = *(const uint4*)(qh + r * HEAD + c * 8);
            *(uint4*)(smB + 18432 + r * 144 + c * 16) = *(const uint4*)(ql + r * HEAD + c * 8);
        }
    }
    __syncthreads();

    // ---- persistent Q A-fragments (4 k-steps x 4 regs, hi & lo) ----
    uint32_t qhiF[4][4], qloF[4][4];
    {
        const uint32_t ra = smb + (uint32_t)(w * 16 + (lane & 15)) * 144 + ((lane >> 4) << 4);
        #pragma unroll
        for (int ks = 0; ks < 4; ks++) {
            LDSM4(qhiF[ks], ra + ks * 32);
            LDSM4(qloF[ks], ra + 18432 + ks * 32);
        }
    }
    __syncthreads();   // before K/V overwrite

    float o[32];
    #pragma unroll
    for (int i = 0; i < 32; i++) o[i] = 0.f;
    float l0 = 0.f, l1 = 0.f;

    const int row_in0 = w * 16 + (lane >> 2);
    const int grow0 = qt * QROWS + row_in0;
    const int grow1 = grow0 + 8;
    const uint32_t lrow  = (uint32_t)(lane & 15) * 144;
    const uint32_t lhalf = ((uint32_t)(lane >> 4)) << 4;

    for (int tl = t0; tl < t1; tl++) {
        __syncthreads();   // previous iter's frag reads done

        // ---- cooperative loads: K hi/lo [kv][c], V^T hi/lo [c][kv] ----
        const __nv_bfloat16* kh = g_khi  + ((size_t)b * SEQ + (size_t)tl * KTILE) * HEAD;
        const __nv_bfloat16* kl = g_klo  + ((size_t)b * SEQ + (size_t)tl * KTILE) * HEAD;
        const __nv_bfloat16* vh = g_vThi + (size_t)b * HEAD * SEQ + (size_t)tl * KTILE;
        const __nv_bfloat16* vl = g_vTlo + (size_t)b * HEAD * SEQ + (size_t)tl * KTILE;
        for (int i = tid; i < 64 * 8; i += 256) {
            int r = i >> 3, c = i & 7;
            *(uint4*)(smB +          r * 144 + c * 16) = *(const uint4*)(kh + (size_t)r * HEAD + c * 8);
            *(uint4*)(smB +  9216 +  r * 144 + c * 16) = *(const uint4*)(kl + (size_t)r * HEAD + c * 8);
            *(uint4*)(smB + 18432 +  r * 144 + c * 16) = *(const uint4*)(vh + (size_t)r * SEQ  + c * 8);
            *(uint4*)(smB + 27648 +  r * 144 + c * 16) = *(const uint4*)(vl + (size_t)r * SEQ  + c * 8);
        }
        __syncthreads();

        // ---- S = Q K^T (3-term split) ----
        float s[32];
        #pragma unroll
        for (int i = 0; i < 32; i++) s[i] = 0.f;

        #pragma unroll
        for (int ks = 0; ks < 4; ks++) {
            #pragma unroll
            for (int pr = 0; pr < 4; pr++) {
                const uint32_t a = smb + (uint32_t)(pr * 16) * 144 + lrow + lhalf + ks * 32;
                uint32_t kh4[4], kl4[4];
                LDSM4(kh4, a);
                LDSM4(kl4, a + 9216);
                float* s0 = s + (2 * pr) * 4;
                float* s1 = s + (2 * pr + 1) * 4;
                MMA16816(s0, qhiF[ks], kh4[0], kh4[2]);
                MMA16816(s0, qhiF[ks], kl4[0], kl4[2]);
                MMA16816(s0, qloF[ks], kh4[0], kh4[2]);
                MMA16816(s1, qhiF[ks], kh4[1], kh4[3]);
                MMA16816(s1, qhiF[ks], kl4[1], kl4[3]);
                MMA16816(s1, qloF[ks], kh4[1], kh4[3]);
            }
        }

        // ---- softmax (no max subtraction) + pack P hi/lo A-frags ----
        const bool diag = (tl >= 2 * qt);
        uint32_t phiF[4][4], ploF[4][4];
        #pragma unroll
        for (int nt = 0; nt < 8; nt++) {
            const float* sp = s + nt * 4;
            float p0, p1, p2, p3;
            if (diag) {
                const int colb = tl * KTILE + nt * 8 + 2 * (lane & 3);
                p0 = (colb     <= grow0) ? __expf(sp[0]) : 0.f;
                p1 = (colb + 1 <= grow0) ? __expf(sp[1]) : 0.f;
                p2 = (colb     <= grow1) ? __expf(sp[2]) : 0.f;
                p3 = (colb + 1 <= grow1) ? __expf(sp[3]) : 0.f;
            } else {
                p0 = __expf(sp[0]); p1 = __expf(sp[1]);
                p2 = __expf(sp[2]); p3 = __expf(sp[3]);
            }
            l0 += p0 + p1;
            l1 += p2 + p3;
            const uint32_t h01 = pack_bf2(p0, p1);
            const uint32_t h23 = pack_bf2(p2, p3);
            __nv_bfloat162 bh01 = *(__nv_bfloat162*)&h01;
            __nv_bfloat162 bh23 = *(__nv_bfloat162*)&h23;
            const uint32_t g01 = pack_bf2(p0 - __bfloat162float(bh01.x),
                                          p1 - __bfloat162float(bh01.y));
            const uint32_t g23 = pack_bf2(p2 - __bfloat162float(bh23.x),
                                          p3 - __bfloat162float(bh23.y));
            const int ks  = nt >> 1;
            const int sel = (nt & 1) << 1;
            phiF[ks][sel]     = h01;
            phiF[ks][sel + 1] = h23;
            ploF[ks][sel]     = g01;
            ploF[ks][sel + 1] = g23;
        }

        // ---- O += P V (3-term split); B = V^T rows = head dims ----
        #pragma unroll
        for (int ks = 0; ks < 4; ks++) {
            #pragma unroll
            for (int pr = 0; pr < 4; pr++) {
                const uint32_t a = smb + 18432 + (uint32_t)(pr * 16) * 144 + lrow + lhalf + ks * 32;
                uint32_t vh4[4], vl4[4];
                LDSM4(vh4, a);
                LDSM4(vl4, a + 9216);
                float* o0 = o + (2 * pr) * 4;
                float* o1 = o + (2 * pr + 1) * 4;
                MMA16816(o0, phiF[ks], vh4[0], vh4[2]);
                MMA16816(o0, phiF[ks], vl4[0], vl4[2]);
                MMA16816(o0, ploF[ks], vh4[0], vh4[2]);
                MMA16816(o1, phiF[ks], vh4[1], vh4[3]);
                MMA16816(o1, phiF[ks], vl4[1], vl4[3]);
                MMA16816(o1, ploF[ks], vh4[1], vh4[3]);
            }
        }
    }

    // ---- reduce l over the quad ----
    l0 += __shfl_xor_sync(0xffffffffu, l0, 1);
    l0 += __shfl_xor_sync(0xffffffffu, l0, 2);
    l1 += __shfl_xor_sync(0xffffffffu, l1, 1);
    l1 += __shfl_xor_sync(0xffffffffu, l1, 2);

    // ---- write partial O and l ----
    const size_t pb = ((size_t)(b * NQT + qt) * MAXCH + ch) * QROWS;
    const int c0 = 2 * (lane & 3);
    #pragma unroll
    for (int nt = 0; nt < 8; nt++) {
        float2 v0 = make_float2(o[nt * 4],     o[nt * 4 + 1]);
        float2 v1 = make_float2(o[nt * 4 + 2], o[nt * 4 + 3]);
        *(float2*)&g_Opart[(pb + row_in0)     * HEAD + nt * 8 + c0] = v0;
        *(float2*)&g_Opart[(pb + row_in0 + 8) * HEAD + nt * 8 + c0] = v1;
    }
    if ((lane & 3) == 0) {
        g_lpart[pb + row_in0]     = l0;
        g_lpart[pb + row_in0 + 8] = l1;
    }
}

// ---------------------------------------------------------------------------
// Kernel 3: combine split-KV partials (pure additive) + normalize.
// ---------------------------------------------------------------------------
__global__ __launch_bounds__(QROWS) void combine_kernel(float* __restrict__ out)
{
    const int b  = blockIdx.x & 3;
    const int qt = blockIdx.x >> 2;
    const int r  = threadIdx.x;
    const int nch = (2 * qt + 2 + CHUNK - 1) / CHUNK;

    float acc[HEAD];
    #pragma unroll
    for (int i = 0; i < HEAD; i++) acc[i] = 0.0f;
    float l = 0.0f;

    for (int ch = 0; ch < nch; ch++) {
        const size_t base = (((size_t)(b * NQT + qt) * MAXCH + ch) * QROWS + r) * HEAD;
        const float4* op = (const float4*)(g_Opart + base);
        #pragma unroll
        for (int i = 0; i < 16; i++) {
            float4 v = op[i];
            acc[4 * i] += v.x; acc[4 * i + 1] += v.y;
            acc[4 * i + 2] += v.z; acc[4 * i + 3] += v.w;
        }
        l += g_lpart[((size_t)(b * NQT + qt) * MAXCH + ch) * QROWS + r];
    }

    const float inv = 1.0f / l;
    float4* dst = (float4*)(out + ((size_t)b * SEQ + (size_t)qt * QROWS + r) * HEAD);
    #pragma unroll
    for (int i = 0; i < 16; i++) {
        dst[i] = make_float4(acc[4 * i] * inv, acc[4 * i + 1] * inv,
                             acc[4 * i + 2] * inv, acc[4 * i + 3] * inv);
    }
}

// ---------------------------------------------------------------------------
extern "C" void kernel_launch(void* const* d_in, const int* in_sizes, int n_in,
                              void* d_out, int out_size)
{
    const float* x  = (const float*)d_in[0];
    const float* Wk = (const float*)d_in[1];
    const float* Wq = (const float*)d_in[2];
    const float* Wv = (const float*)d_in[3];
    float* out = (float*)d_out;

    qkv_proj_kernel<<<dim3(BATCH * SEQ / 128, 3), 256>>>(x, Wk, Wq, Wv);
    attn_kernel<<<BATCH * NQT * MAXCH, 256>>>();
    combine_kernel<<<BATCH * NQT, QROWS>>>(out);
}

// round 10
// speedup vs baseline: 1.3762x; 1.3762x over previous
#include <cuda_runtime.h>
#include <cuda_bf16.h>
#include <cstdint>

#define HEAD   64
#define SEQ    4096
#define BATCH  4
#define SCALE  0.125f
#define QROWS  128
#define NQT    (SEQ / QROWS)     // 32
#define KTILE  64
#define CHUNK  8                 // kv tiles per CTA chunk
#define MAXCH  8
#define SPITCH 72                // smem row pitch in bf16 (144 B)

// ---------------------------------------------------------------------------
// Scratch
// ---------------------------------------------------------------------------
__device__ __align__(16) __nv_bfloat16 g_qhi [BATCH * SEQ * HEAD];  // [b][t][c] pre-scaled
__device__ __align__(16) __nv_bfloat16 g_qlo [BATCH * SEQ * HEAD];
__device__ __align__(16) __nv_bfloat16 g_khi [BATCH * SEQ * HEAD];  // [b][t][c]
__device__ __align__(16) __nv_bfloat16 g_klo [BATCH * SEQ * HEAD];
__device__ __align__(16) __nv_bfloat16 g_vThi[BATCH * HEAD * SEQ];  // [b][c][t]
__device__ __align__(16) __nv_bfloat16 g_vTlo[BATCH * HEAD * SEQ];
__device__ __align__(16) float g_Opart[BATCH * NQT * MAXCH * QROWS * HEAD];
__device__ __align__(16) float g_lpart[BATCH * NQT * MAXCH * QROWS];

// ---------------------------------------------------------------------------
// PTX helpers (generic sm_80+ features only — target is plain sm_103!)
// ---------------------------------------------------------------------------
__device__ __forceinline__ uint32_t smem_u32(const void* p) {
    uint32_t a;
    asm("{ .reg .u64 t; cvta.to.shared.u64 t, %1; cvt.u32.u64 %0, t; }"
        : "=r"(a) : "l"(p));
    return a;
}

#define LDSM4(r, addr) \
    asm volatile("ldmatrix.sync.aligned.m8n8.x4.shared.b16 {%0,%1,%2,%3}, [%4];" \
        : "=r"((r)[0]), "=r"((r)[1]), "=r"((r)[2]), "=r"((r)[3]) : "r"(addr))

#define MMA16816(d, a, b0, b1) \
    asm volatile("mma.sync.aligned.m16n8k16.row.col.f32.bf16.bf16.f32 " \
        "{%0,%1,%2,%3}, {%4,%5,%6,%7}, {%8,%9}, {%0,%1,%2,%3};" \
        : "+f"((d)[0]), "+f"((d)[1]), "+f"((d)[2]), "+f"((d)[3]) \
        : "r"((a)[0]), "r"((a)[1]), "r"((a)[2]), "r"((a)[3]), "r"(b0), "r"(b1))

__device__ __forceinline__ uint32_t pack_bf2(float a, float b) {
    __nv_bfloat162 h = __floats2bfloat162_rn(a, b);
    return *(uint32_t*)&h;
}

// ---------------------------------------------------------------------------
// Kernel 1: QKV projection -> bf16 hi/lo splits. (R5 scalar-smem version:
// broadcast-heavy scalar LDS measured 36.1us; float4 variant measured 86us.)
// grid = (BATCH*SEQ/128, 3 matrices), 256 threads; thread tile 4 rows x 8 out.
// ---------------------------------------------------------------------------
__global__ __launch_bounds__(256) void qkv_proj_kernel(
    const float* __restrict__ x,  const float* __restrict__ Wk,
    const float* __restrict__ Wq, const float* __restrict__ Wv)
{
    __shared__ float xs[128][65];
    __shared__ float ws[64][65];

    const int tid  = threadIdx.x;
    const int row0 = blockIdx.x * 128;
    const int m    = blockIdx.y;

    const float* W = (m == 0) ? Wq : (m == 1) ? Wk : Wv;

    for (int i = tid; i < 128 * 64; i += 256) {
        int r = i >> 6, c = i & 63;
        xs[r][c] = x[(size_t)(row0 + r) * HEAD + c];
    }
    for (int i = tid; i < 64 * 64; i += 256) {
        int r = i >> 6, c = i & 63;
        ws[r][c] = W[r * HEAD + c];
    }
    __syncthreads();

    const int oo = tid & 7;
    const int rr = tid >> 3;
    const int ob = oo * 8;
    const int rb = rr * 4;

    float acc[4][8];
    #pragma unroll
    for (int j = 0; j < 4; j++)
        #pragma unroll
        for (int k = 0; k < 8; k++) acc[j][k] = 0.f;

    #pragma unroll 4
    for (int c = 0; c < 64; c++) {
        float xv[4], wv[8];
        #pragma unroll
        for (int j = 0; j < 4; j++) xv[j] = xs[rb + j][c];
        #pragma unroll
        for (int k = 0; k < 8; k++) wv[k] = ws[ob + k][c];
        #pragma unroll
        for (int j = 0; j < 4; j++)
            #pragma unroll
            for (int k = 0; k < 8; k++)
                acc[j][k] += xv[j] * wv[k];
    }

    const int b  = row0 / SEQ;
    const int tb = (row0 % SEQ) + rb;
    const float sc = (m == 0) ? SCALE : 1.0f;

    #pragma unroll
    for (int j = 0; j < 4; j++) {
        __nv_bfloat16 hi[8], lo[8];
        #pragma unroll
        for (int k = 0; k < 8; k++) {
            float v = acc[j][k] * sc;
            hi[k] = __float2bfloat16(v);
            lo[k] = __float2bfloat16(v - __bfloat162float(hi[k]));
        }
        if (m < 2) {
            size_t ofs = ((size_t)b * SEQ + tb + j) * HEAD + ob;
            __nv_bfloat16* dh = (m == 0 ? g_qhi : g_khi) + ofs;
            __nv_bfloat16* dl = (m == 0 ? g_qlo : g_klo) + ofs;
            uint32_t ph[4], pl[4];
            #pragma unroll
            for (int k = 0; k < 4; k++) {
                __nv_bfloat162 h2; h2.x = hi[2*k]; h2.y = hi[2*k+1];
                __nv_bfloat162 l2; l2.x = lo[2*k]; l2.y = lo[2*k+1];
                ph[k] = *(uint32_t*)&h2;
                pl[k] = *(uint32_t*)&l2;
            }
            *(uint4*)dh = make_uint4(ph[0], ph[1], ph[2], ph[3]);
            *(uint4*)dl = make_uint4(pl[0], pl[1], pl[2], pl[3]);
        } else {
            #pragma unroll
            for (int k = 0; k < 8; k++) {
                size_t ofs = ((size_t)b * HEAD + (ob + k)) * SEQ + tb + j;
                g_vThi[ofs] = hi[k];
                g_vTlo[ofs] = lo[k];
            }
        }
    }
}

// ---------------------------------------------------------------------------
// Kernel 2: FA2-style mma.sync bf16 causal attention (hi/lo split, no max).
// CTA = (b, 128-row q tile, kv chunk of <=8 64-wide kv tiles), 256 threads.
// __launch_bounds__(256,2): occupancy-2 is load-bearing (R5 regression proof).
// ---------------------------------------------------------------------------
__global__ __launch_bounds__(256, 2) void attn_kernel()
{
    __shared__ __align__(16) __nv_bfloat16 sm[4 * 64 * SPITCH];

    const int tid  = threadIdx.x;
    const int w    = tid >> 5;
    const int lane = tid & 31;

    const int bx = blockIdx.x;
    const int b  = bx & 3;
    const int qt = (NQT - 1) - ((bx >> 2) & 31);  // heavy tiles first
    const int ch = bx >> 7;

    const int ntiles = 2 * qt + 2;
    const int t0 = ch * CHUNK;
    const int t1 = (t0 + CHUNK < ntiles) ? (t0 + CHUNK) : ntiles;
    if (t0 >= t1) return;

    const uint32_t smb = smem_u32(sm);
    uint8_t* smB = (uint8_t*)sm;

    // ---- stage Q hi (bytes [0,18432)) and Q lo (bytes [18432,36864)) ----
    {
        const __nv_bfloat16* qh = g_qhi + ((size_t)b * SEQ + (size_t)qt * QROWS) * HEAD;
        const __nv_bfloat16* ql = g_qlo + ((size_t)b * SEQ + (size_t)qt * QROWS) * HEAD;
        for (int i = tid; i < 128 * 8; i += 256) {
            int r = i >> 3, c = i & 7;
            *(uint4*)(smB + r * 144 + c * 16)         = *(const uint4*)(qh + r * HEAD + c * 8);
            *(uint4*)(smB + 18432 + r * 144 + c * 16) = *(const uint4*)(ql + r * HEAD + c * 8);
        }
    }
    __syncthreads();

    // ---- persistent Q A-fragments (4 k-steps x 4 regs, hi & lo) ----
    uint32_t qhiF[4][4], qloF[4][4];
    {
        const uint32_t ra = smb + (uint32_t)(w * 16 + (lane & 15)) * 144 + ((lane >> 4) << 4);
        #pragma unroll
        for (int ks = 0; ks < 4; ks++) {
            LDSM4(qhiF[ks], ra + ks * 32);
            LDSM4(qloF[ks], ra + 18432 + ks * 32);
        }
    }
    __syncthreads();   // before K/V overwrite

    float o[32];
    #pragma unroll
    for (int i = 0; i < 32; i++) o[i] = 0.f;
    float l0 = 0.f, l1 = 0.f;

    const int row_in0 = w * 16 + (lane >> 2);
    const int grow0 = qt * QROWS + row_in0;
    const int grow1 = grow0 + 8;
    const uint32_t lrow  = (uint32_t)(lane & 15) * 144;
    const uint32_t lhalf = ((uint32_t)(lane >> 4)) << 4;

    for (int tl = t0; tl < t1; tl++) {
        __syncthreads();   // previous iter's frag reads done

        // ---- cooperative loads: K hi/lo [kv][c], V^T hi/lo [c][kv] ----
        const __nv_bfloat16* kh = g_khi  + ((size_t)b * SEQ + (size_t)tl * KTILE) * HEAD;
        const __nv_bfloat16* kl = g_klo  + ((size_t)b * SEQ + (size_t)tl * KTILE) * HEAD;
        const __nv_bfloat16* vh = g_vThi + (size_t)b * HEAD * SEQ + (size_t)tl * KTILE;
        const __nv_bfloat16* vl = g_vTlo + (size_t)b * HEAD * SEQ + (size_t)tl * KTILE;
        for (int i = tid; i < 64 * 8; i += 256) {
            int r = i >> 3, c = i & 7;
            *(uint4*)(smB +          r * 144 + c * 16) = *(const uint4*)(kh + (size_t)r * HEAD + c * 8);
            *(uint4*)(smB +  9216 +  r * 144 + c * 16) = *(const uint4*)(kl + (size_t)r * HEAD + c * 8);
            *(uint4*)(smB + 18432 +  r * 144 + c * 16) = *(const uint4*)(vh + (size_t)r * SEQ  + c * 8);
            *(uint4*)(smB + 27648 +  r * 144 + c * 16) = *(const uint4*)(vl + (size_t)r * SEQ  + c * 8);
        }
        __syncthreads();

        // ---- S = Q K^T (3-term split) ----
        float s[32];
        #pragma unroll
        for (int i = 0; i < 32; i++) s[i] = 0.f;

        #pragma unroll
        for (int ks = 0; ks < 4; ks++) {
            #pragma unroll
            for (int pr = 0; pr < 4; pr++) {
                const uint32_t a = smb + (uint32_t)(pr * 16) * 144 + lrow + lhalf + ks * 32;
                uint32_t kh4[4], kl4[4];
                LDSM4(kh4, a);
                LDSM4(kl4, a + 9216);
                float* s0 = s + (2 * pr) * 4;
                float* s1 = s + (2 * pr + 1) * 4;
                MMA16816(s0, qhiF[ks], kh4[0], kh4[2]);
                MMA16816(s0, qhiF[ks], kl4[0], kl4[2]);
                MMA16816(s0, qloF[ks], kh4[0], kh4[2]);
                MMA16816(s1, qhiF[ks], kh4[1], kh4[3]);
                MMA16816(s1, qhiF[ks], kl4[1], kl4[3]);
                MMA16816(s1, qloF[ks], kh4[1], kh4[3]);
            }
        }

        // ---- softmax (no max subtraction) + pack P hi/lo A-frags ----
        const bool diag = (tl >= 2 * qt);
        uint32_t phiF[4][4], ploF[4][4];
        #pragma unroll
        for (int nt = 0; nt < 8; nt++) {
            const float* sp = s + nt * 4;
            float p0, p1, p2, p3;
            if (diag) {
                const int colb = tl * KTILE + nt * 8 + 2 * (lane & 3);
                p0 = (colb     <= grow0) ? __expf(sp[0]) : 0.f;
                p1 = (colb + 1 <= grow0) ? __expf(sp[1]) : 0.f;
                p2 = (colb     <= grow1) ? __expf(sp[2]) : 0.f;
                p3 = (colb + 1 <= grow1) ? __expf(sp[3]) : 0.f;
            } else {
                p0 = __expf(sp[0]); p1 = __expf(sp[1]);
                p2 = __expf(sp[2]); p3 = __expf(sp[3]);
            }
            l0 += p0 + p1;
            l1 += p2 + p3;
            const uint32_t h01 = pack_bf2(p0, p1);
            const uint32_t h23 = pack_bf2(p2, p3);
            __nv_bfloat162 bh01 = *(__nv_bfloat162*)&h01;
            __nv_bfloat162 bh23 = *(__nv_bfloat162*)&h23;
            const uint32_t g01 = pack_bf2(p0 - __bfloat162float(bh01.x),
                                          p1 - __bfloat162float(bh01.y));
            const uint32_t g23 = pack_bf2(p2 - __bfloat162float(bh23.x),
                                          p3 - __bfloat162float(bh23.y));
            const int ks  = nt >> 1;
            const int sel = (nt & 1) << 1;
            phiF[ks][sel]     = h01;
            phiF[ks][sel + 1] = h23;
            ploF[ks][sel]     = g01;
            ploF[ks][sel + 1] = g23;
        }

        // ---- O += P V (3-term split); B = V^T rows = head dims ----
        #pragma unroll
        for (int ks = 0; ks < 4; ks++) {
            #pragma unroll
            for (int pr = 0; pr < 4; pr++) {
                const uint32_t a = smb + 18432 + (uint32_t)(pr * 16) * 144 + lrow + lhalf + ks * 32;
                uint32_t vh4[4], vl4[4];
                LDSM4(vh4, a);
                LDSM4(vl4, a + 9216);
                float* o0 = o + (2 * pr) * 4;
                float* o1 = o + (2 * pr + 1) * 4;
                MMA16816(o0, phiF[ks], vh4[0], vh4[2]);
                MMA16816(o0, phiF[ks], vl4[0], vl4[2]);
                MMA16816(o0, ploF[ks], vh4[0], vh4[2]);
                MMA16816(o1, phiF[ks], vh4[1], vh4[3]);
                MMA16816(o1, phiF[ks], vl4[1], vl4[3]);
                MMA16816(o1, ploF[ks], vh4[1], vh4[3]);
            }
        }
    }

    // ---- reduce l over the quad ----
    l0 += __shfl_xor_sync(0xffffffffu, l0, 1);
    l0 += __shfl_xor_sync(0xffffffffu, l0, 2);
    l1 += __shfl_xor_sync(0xffffffffu, l1, 1);
    l1 += __shfl_xor_sync(0xffffffffu, l1, 2);

    // ---- write partial O and l ----
    const size_t pb = ((size_t)(b * NQT + qt) * MAXCH + ch) * QROWS;
    const int c0 = 2 * (lane & 3);
    #pragma unroll
    for (int nt = 0; nt < 8; nt++) {
        float2 v0 = make_float2(o[nt * 4],     o[nt * 4 + 1]);
        float2 v1 = make_float2(o[nt * 4 + 2], o[nt * 4 + 3]);
        *(float2*)&g_Opart[(pb + row_in0)     * HEAD + nt * 8 + c0] = v0;
        *(float2*)&g_Opart[(pb + row_in0 + 8) * HEAD + nt * 8 + c0] = v1;
    }
    if ((lane & 3) == 0) {
        g_lpart[pb + row_in0]     = l0;
        g_lpart[pb + row_in0 + 8] = l1;
    }
}

// ---------------------------------------------------------------------------
// Kernel 3: combine split-KV partials (pure additive) + normalize.
// ---------------------------------------------------------------------------
__global__ __launch_bounds__(QROWS) void combine_kernel(float* __restrict__ out)
{
    const int b  = blockIdx.x & 3;
    const int qt = blockIdx.x >> 2;
    const int r  = threadIdx.x;
    const int nch = (2 * qt + 2 + CHUNK - 1) / CHUNK;

    float acc[HEAD];
    #pragma unroll
    for (int i = 0; i < HEAD; i++) acc[i] = 0.0f;
    float l = 0.0f;

    for (int ch = 0; ch < nch; ch++) {
        const size_t base = (((size_t)(b * NQT + qt) * MAXCH + ch) * QROWS + r) * HEAD;
        const float4* op = (const float4*)(g_Opart + base);
        #pragma unroll
        for (int i = 0; i < 16; i++) {
            float4 v = op[i];
            acc[4 * i] += v.x; acc[4 * i + 1] += v.y;
            acc[4 * i + 2] += v.z; acc[4 * i + 3] += v.w;
        }
        l += g_lpart[((size_t)(b * NQT + qt) * MAXCH + ch) * QROWS + r];
    }

    const float inv = 1.0f / l;
    float4* dst = (float4*)(out + ((size_t)b * SEQ + (size_t)qt * QROWS + r) * HEAD);
    #pragma unroll
    for (int i = 0; i < 16; i++) {
        dst[i] = make_float4(acc[4 * i] * inv, acc[4 * i + 1] * inv,
                             acc[4 * i + 2] * inv, acc[4 * i + 3] * inv);
    }
}

// ---------------------------------------------------------------------------
extern "C" void kernel_launch(void* const* d_in, const int* in_sizes, int n_in,
                              void* d_out, int out_size)
{
    const float* x  = (const float*)d_in[0];
    const float* Wk = (const float*)d_in[1];
    const float* Wq = (const float*)d_in[2];
    const float* Wv = (const float*)d_in[3];
    float* out = (float*)d_out;

    qkv_proj_kernel<<<dim3(BATCH * SEQ / 128, 3), 256>>>(x, Wk, Wq, Wv);
    attn_kernel<<<BATCH * NQT * MAXCH, 256>>>();
    combine_kernel<<<BATCH * NQT, QROWS>>>(out);
}

// round 13
// speedup vs baseline: 2.3644x; 1.7181x over previous
#include <cuda_runtime.h>
#include <cuda_fp16.h>
#include <cstdint>

#define HEAD   64
#define SEQ    4096
#define BATCH  4
#define SCALE  0.125f
#define QROWS  128
#define NQT    (SEQ / QROWS)     // 32
#define KTILE  64
#define CHUNK  8                 // kv tiles per CTA chunk
#define MAXCH  8

// ---------------------------------------------------------------------------
// Scratch (fp16 single-precision operands)
// ---------------------------------------------------------------------------
__device__ __align__(16) __half g_qh [BATCH * SEQ * HEAD];   // [b][t][c] pre-scaled
__device__ __align__(16) __half g_kh [BATCH * SEQ * HEAD];   // [b][t][c]
__device__ __align__(16) __half g_vTh[BATCH * HEAD * SEQ];   // [b][c][t]
__device__ __align__(16) float g_Opart[BATCH * NQT * MAXCH * QROWS * HEAD];
__device__ __align__(16) float g_lpart[BATCH * NQT * MAXCH * QROWS];

// ---------------------------------------------------------------------------
// PTX helpers (generic sm_80+ only — target is plain sm_103)
// ---------------------------------------------------------------------------
__device__ __forceinline__ uint32_t smem_u32(const void* p) {
    uint32_t a;
    asm("{ .reg .u64 t; cvta.to.shared.u64 t, %1; cvt.u32.u64 %0, t; }"
        : "=r"(a) : "l"(p));
    return a;
}

#define LDSM4(r, addr) \
    asm volatile("ldmatrix.sync.aligned.m8n8.x4.shared.b16 {%0,%1,%2,%3}, [%4];" \
        : "=r"((r)[0]), "=r"((r)[1]), "=r"((r)[2]), "=r"((r)[3]) : "r"(addr))

#define MMA16816F16(d, a, b0, b1) \
    asm volatile("mma.sync.aligned.m16n8k16.row.col.f32.f16.f16.f32 " \
        "{%0,%1,%2,%3}, {%4,%5,%6,%7}, {%8,%9}, {%0,%1,%2,%3};" \
        : "+f"((d)[0]), "+f"((d)[1]), "+f"((d)[2]), "+f"((d)[3]) \
        : "r"((a)[0]), "r"((a)[1]), "r"((a)[2]), "r"((a)[3]), "r"(b0), "r"(b1))

__device__ __forceinline__ uint32_t pack_h2(float a, float b) {
    __half2 h = __floats2half2_rn(a, b);
    return *(uint32_t*)&h;
}

// ---------------------------------------------------------------------------
// Kernel 1: QKV projection -> fp16 (scalar-broadcast smem GEMM, measured 36us
// in bf16-double form; halving store traffic here).
// ---------------------------------------------------------------------------
__global__ __launch_bounds__(256) void qkv_proj_kernel(
    const float* __restrict__ x,  const float* __restrict__ Wk,
    const float* __restrict__ Wq, const float* __restrict__ Wv)
{
    __shared__ float xs[128][65];
    __shared__ float ws[64][65];

    const int tid  = threadIdx.x;
    const int row0 = blockIdx.x * 128;
    const int m    = blockIdx.y;

    const float* W = (m == 0) ? Wq : (m == 1) ? Wk : Wv;

    for (int i = tid; i < 128 * 64; i += 256) {
        int r = i >> 6, c = i & 63;
        xs[r][c] = x[(size_t)(row0 + r) * HEAD + c];
    }
    for (int i = tid; i < 64 * 64; i += 256) {
        int r = i >> 6, c = i & 63;
        ws[r][c] = W[r * HEAD + c];
    }
    __syncthreads();

    const int oo = tid & 7;
    const int rr = tid >> 3;
    const int ob = oo * 8;
    const int rb = rr * 4;

    float acc[4][8];
    #pragma unroll
    for (int j = 0; j < 4; j++)
        #pragma unroll
        for (int k = 0; k < 8; k++) acc[j][k] = 0.f;

    #pragma unroll 4
    for (int c = 0; c < 64; c++) {
        float xv[4], wv[8];
        #pragma unroll
        for (int j = 0; j < 4; j++) xv[j] = xs[rb + j][c];
        #pragma unroll
        for (int k = 0; k < 8; k++) wv[k] = ws[ob + k][c];
        #pragma unroll
        for (int j = 0; j < 4; j++)
            #pragma unroll
            for (int k = 0; k < 8; k++)
                acc[j][k] += xv[j] * wv[k];
    }

    const int b  = row0 / SEQ;
    const int tb = (row0 % SEQ) + rb;
    const float sc = (m == 0) ? SCALE : 1.0f;

    #pragma unroll
    for (int j = 0; j < 4; j++) {
        if (m < 2) {
            uint32_t pk[4];
            #pragma unroll
            for (int k = 0; k < 4; k++)
                pk[k] = pack_h2(acc[j][2 * k] * sc, acc[j][2 * k + 1] * sc);
            size_t ofs = ((size_t)b * SEQ + tb + j) * HEAD + ob;
            *(uint4*)((m == 0 ? g_qh : g_kh) + ofs) = make_uint4(pk[0], pk[1], pk[2], pk[3]);
        } else {
            #pragma unroll
            for (int k = 0; k < 8; k++) {
                size_t ofs = ((size_t)b * HEAD + (ob + k)) * SEQ + tb + j;
                g_vTh[ofs] = __float2half_rn(acc[j][k]);
            }
        }
    }
}

// ---------------------------------------------------------------------------
// Kernel 2: FA2-style fp16 mma.sync causal attention, double-buffered K/V,
// one __syncthreads per KV tile, LDG prefetch overlapped with compute.
// CTA = (b, 128-row q tile, kv chunk of <=8 tiles), 256 threads, occ 2.
// smem: 2 buffers x (K 9216B + V 9216B) = 36864B. Q staged in buf1.
// ---------------------------------------------------------------------------
__global__ __launch_bounds__(256, 2) void attn_kernel()
{
    __shared__ __align__(16) uint8_t sm[2 * 18432];

    const int tid  = threadIdx.x;
    const int w    = tid >> 5;
    const int lane = tid & 31;

    const int bx = blockIdx.x;
    const int b  = bx & 3;
    const int qt = (NQT - 1) - ((bx >> 2) & 31);  // heavy tiles first
    const int ch = bx >> 7;

    const int ntiles = 2 * qt + 2;
    const int t0 = ch * CHUNK;
    const int t1 = (t0 + CHUNK < ntiles) ? (t0 + CHUNK) : ntiles;
    if (t0 >= t1) return;

    const uint32_t smb = smem_u32(sm);
    uint8_t* smB = (uint8_t*)sm;

    // ---- stage Q in buf1 region [18432, 36864) and build A-fragments ----
    {
        const __half* qh = g_qh + ((size_t)b * SEQ + (size_t)qt * QROWS) * HEAD;
        for (int i = tid; i < 128 * 8; i += 256) {
            int r = i >> 3, c = i & 7;
            *(uint4*)(smB + 18432 + r * 144 + c * 16) = *(const uint4*)(qh + r * HEAD + c * 8);
        }
    }
    __syncthreads();

    uint32_t qF[4][4];
    {
        const uint32_t ra = smb + 18432 + (uint32_t)(w * 16 + (lane & 15)) * 144 + ((lane >> 4) << 4);
        #pragma unroll
        for (int ks = 0; ks < 4; ks++) LDSM4(qF[ks], ra + ks * 32);
    }
    // NOTE: no sync needed here before the t0 STS into buf0 (disjoint from buf1);
    // the loop-top sync orders buf1 overwrite (first STS to buf1 happens after
    // every warp's LDSM via the iter-0 barrier).

    const __half* kbase = g_kh  + (size_t)b * SEQ * HEAD;
    const __half* vbase = g_vTh + (size_t)b * HEAD * SEQ;

    // per-thread load slots: K rows: entries e = tid, tid+256 ; V same.
    const int e0r = tid >> 3,          e0c = tid & 7;          // entry tid
    const int e1r = (tid + 256) >> 3,  e1c = tid & 7;          // entry tid+256

    // ---- prologue: load tile t0 and store into buf0 ----
    {
        const __half* kp = kbase + (size_t)t0 * KTILE * HEAD;
        const __half* vp = vbase + (size_t)t0 * KTILE;
        uint4 k0 = *(const uint4*)(kp + (size_t)e0r * HEAD + e0c * 8);
        uint4 k1 = *(const uint4*)(kp + (size_t)e1r * HEAD + e1c * 8);
        uint4 v0 = *(const uint4*)(vp + (size_t)e0r * SEQ  + e0c * 8);
        uint4 v1 = *(const uint4*)(vp + (size_t)e1r * SEQ  + e1c * 8);
        *(uint4*)(smB + e0r * 144 + e0c * 16)        = k0;
        *(uint4*)(smB + e1r * 144 + e1c * 16)        = k1;
        *(uint4*)(smB + 9216 + e0r * 144 + e0c * 16) = v0;
        *(uint4*)(smB + 9216 + e1r * 144 + e1c * 16) = v1;
    }

    float o[32];
    #pragma unroll
    for (int i = 0; i < 32; i++) o[i] = 0.f;
    float l0 = 0.f, l1 = 0.f;

    const int row_in0 = w * 16 + (lane >> 2);
    const int grow0 = qt * QROWS + row_in0;
    const int grow1 = grow0 + 8;
    const uint32_t lrow  = (uint32_t)(lane & 15) * 144;
    const uint32_t lhalf = ((uint32_t)(lane >> 4)) << 4;

    for (int tl = t0; tl < t1; tl++) {
        const uint32_t cur = (uint32_t)((tl - t0) & 1) * 18432;
        const uint32_t nxt = cur ^ 18432;

        __syncthreads();   // buf[cur] stores visible; all warps done reading buf[nxt]

        // ---- prefetch next tile into registers (latency hidden by compute) ----
        uint4 k0, k1, v0, v1;
        const bool have_next = (tl + 1 < t1);
        if (have_next) {
            const __half* kp = kbase + (size_t)(tl + 1) * KTILE * HEAD;
            const __half* vp = vbase + (size_t)(tl + 1) * KTILE;
            k0 = *(const uint4*)(kp + (size_t)e0r * HEAD + e0c * 8);
            k1 = *(const uint4*)(kp + (size_t)e1r * HEAD + e1c * 8);
            v0 = *(const uint4*)(vp + (size_t)e0r * SEQ  + e0c * 8);
            v1 = *(const uint4*)(vp + (size_t)e1r * SEQ  + e1c * 8);
        }

        // ---- S = Q K^T (single fp16 pass) ----
        float s[32];
        #pragma unroll
        for (int i = 0; i < 32; i++) s[i] = 0.f;

        #pragma unroll
        for (int ks = 0; ks < 4; ks++) {
            #pragma unroll
            for (int pr = 0; pr < 4; pr++) {
                const uint32_t a = smb + cur + (uint32_t)(pr * 16) * 144 + lrow + lhalf + ks * 32;
                uint32_t k4[4];
                LDSM4(k4, a);
                MMA16816F16(s + (2 * pr) * 4,     qF[ks], k4[0], k4[2]);
                MMA16816F16(s + (2 * pr + 1) * 4, qF[ks], k4[1], k4[3]);
            }
        }

        // ---- softmax (no max subtraction) + pack P fp16 A-frags ----
        const bool diag = (tl >= 2 * qt);
        uint32_t pF[4][4];
        #pragma unroll
        for (int nt = 0; nt < 8; nt++) {
            const float* sp = s + nt * 4;
            float p0, p1, p2, p3;
            if (diag) {
                const int colb = tl * KTILE + nt * 8 + 2 * (lane & 3);
                p0 = (colb     <= grow0) ? __expf(sp[0]) : 0.f;
                p1 = (colb + 1 <= grow0) ? __expf(sp[1]) : 0.f;
                p2 = (colb     <= grow1) ? __expf(sp[2]) : 0.f;
                p3 = (colb + 1 <= grow1) ? __expf(sp[3]) : 0.f;
            } else {
                p0 = __expf(sp[0]); p1 = __expf(sp[1]);
                p2 = __expf(sp[2]); p3 = __expf(sp[3]);
            }
            l0 += p0 + p1;
            l1 += p2 + p3;
            const int ks  = nt >> 1;
            const int sel = (nt & 1) << 1;
            pF[ks][sel]     = pack_h2(p0, p1);
            pF[ks][sel + 1] = pack_h2(p2, p3);
        }

        // ---- O += P V (single fp16 pass) ----
        #pragma unroll
        for (int ks = 0; ks < 4; ks++) {
            #pragma unroll
            for (int pr = 0; pr < 4; pr++) {
                const uint32_t a = smb + cur + 9216 + (uint32_t)(pr * 16) * 144 + lrow + lhalf + ks * 32;
                uint32_t v4[4];
                LDSM4(v4, a);
                MMA16816F16(o + (2 * pr) * 4,     pF[ks], v4[0], v4[2]);
                MMA16816F16(o + (2 * pr + 1) * 4, pF[ks], v4[1], v4[3]);
            }
        }

        // ---- store prefetched tile into the other buffer ----
        if (have_next) {
            *(uint4*)(smB + nxt + e0r * 144 + e0c * 16)        = k0;
            *(uint4*)(smB + nxt + e1r * 144 + e1c * 16)        = k1;
            *(uint4*)(smB + nxt + 9216 + e0r * 144 + e0c * 16) = v0;
            *(uint4*)(smB + nxt + 9216 + e1r * 144 + e1c * 16) = v1;
        }
    }

    // ---- reduce l over the quad ----
    l0 += __shfl_xor_sync(0xffffffffu, l0, 1);
    l0 += __shfl_xor_sync(0xffffffffu, l0, 2);
    l1 += __shfl_xor_sync(0xffffffffu, l1, 1);
    l1 += __shfl_xor_sync(0xffffffffu, l1, 2);

    // ---- write partial O and l ----
    const size_t pb = ((size_t)(b * NQT + qt) * MAXCH + ch) * QROWS;
    const int c0 = 2 * (lane & 3);
    #pragma unroll
    for (int nt = 0; nt < 8; nt++) {
        float2 va = make_float2(o[nt * 4],     o[nt * 4 + 1]);
        float2 vb = make_float2(o[nt * 4 + 2], o[nt * 4 + 3]);
        *(float2*)&g_Opart[(pb + row_in0)     * HEAD + nt * 8 + c0] = va;
        *(float2*)&g_Opart[(pb + row_in0 + 8) * HEAD + nt * 8 + c0] = vb;
    }
    if ((lane & 3) == 0) {
        g_lpart[pb + row_in0]     = l0;
        g_lpart[pb + row_in0 + 8] = l1;
    }
}

// ---------------------------------------------------------------------------
// Kernel 3: combine split-KV partials (pure additive) + normalize.
// ---------------------------------------------------------------------------
__global__ __launch_bounds__(QROWS) void combine_kernel(float* __restrict__ out)
{
    const int b  = blockIdx.x & 3;
    const int qt = blockIdx.x >> 2;
    const int r  = threadIdx.x;
    const int nch = (2 * qt + 2 + CHUNK - 1) / CHUNK;

    float acc[HEAD];
    #pragma unroll
    for (int i = 0; i < HEAD; i++) acc[i] = 0.0f;
    float l = 0.0f;

    for (int ch = 0; ch < nch; ch++) {
        const size_t base = (((size_t)(b * NQT + qt) * MAXCH + ch) * QROWS + r) * HEAD;
        const float4* op = (const float4*)(g_Opart + base);
        #pragma unroll
        for (int i = 0; i < 16; i++) {
            float4 v = op[i];
            acc[4 * i] += v.x; acc[4 * i + 1] += v.y;
            acc[4 * i + 2] += v.z; acc[4 * i + 3] += v.w;
        }
        l += g_lpart[((size_t)(b * NQT + qt) * MAXCH + ch) * QROWS + r];
    }

    const float inv = 1.0f / l;
    float4* dst = (float4*)(out + ((size_t)b * SEQ + (size_t)qt * QROWS + r) * HEAD);
    #pragma unroll
    for (int i = 0; i < 16; i++) {
        dst[i] = make_float4(acc[4 * i] * inv, acc[4 * i + 1] * inv,
                             acc[4 * i + 2] * inv, acc[4 * i + 3] * inv);
    }
}

// ---------------------------------------------------------------------------
extern "C" void kernel_launch(void* const* d_in, const int* in_sizes, int n_in,
                              void* d_out, int out_size)
{
    const float* x  = (const float*)d_in[0];
    const float* Wk = (const float*)d_in[1];
    const float* Wq = (const float*)d_in[2];
    const float* Wv = (const float*)d_in[3];
    float* out = (float*)d_out;

    qkv_proj_kernel<<<dim3(BATCH * SEQ / 128, 3), 256>>>(x, Wk, Wq, Wv);
    attn_kernel<<<BATCH * NQT * MAXCH, 256>>>();
    combine_kernel<<<BATCH * NQT, QROWS>>>(out);
}

// round 14
// speedup vs baseline: 3.1421x; 1.3289x over previous
#include <cuda_runtime.h>
#include <cuda_fp16.h>
#include <cstdint>

#define HEAD   64
#define SEQ    4096
#define BATCH  4
#define SCALE_LOG2E 0.18033688011112042f   // 0.125 * log2(e); exp(S)=exp2(S*this/0.125...)
#define QROWS  128
#define NQT    (SEQ / QROWS)     // 32
#define KTILE  64
#define CHUNK  8                 // kv tiles per CTA chunk
#define MAXCH  8

// ---------------------------------------------------------------------------
// Scratch (fp16 operands; q pre-scaled by SCALE*log2e so softmax uses ex2)
// ---------------------------------------------------------------------------
__device__ __align__(16) __half g_qh [BATCH * SEQ * HEAD];   // [b][t][c]
__device__ __align__(16) __half g_kh [BATCH * SEQ * HEAD];   // [b][t][c]
__device__ __align__(16) __half g_vTh[BATCH * HEAD * SEQ];   // [b][c][t]
__device__ __align__(16) float g_Opart[BATCH * NQT * MAXCH * QROWS * HEAD];
__device__ __align__(16) float g_lpart[BATCH * NQT * MAXCH * QROWS];

// ---------------------------------------------------------------------------
// PTX helpers (generic sm_80+ only — target is plain sm_103)
// ---------------------------------------------------------------------------
__device__ __forceinline__ uint32_t smem_u32(const void* p) {
    uint32_t a;
    asm("{ .reg .u64 t; cvta.to.shared.u64 t, %1; cvt.u32.u64 %0, t; }"
        : "=r"(a) : "l"(p));
    return a;
}

#define LDSM4(r, addr) \
    asm volatile("ldmatrix.sync.aligned.m8n8.x4.shared.b16 {%0,%1,%2,%3}, [%4];" \
        : "=r"((r)[0]), "=r"((r)[1]), "=r"((r)[2]), "=r"((r)[3]) : "r"(addr))

#define MMA16816F16(d, a, b0, b1) \
    asm volatile("mma.sync.aligned.m16n8k16.row.col.f32.f16.f16.f32 " \
        "{%0,%1,%2,%3}, {%4,%5,%6,%7}, {%8,%9}, {%0,%1,%2,%3};" \
        : "+f"((d)[0]), "+f"((d)[1]), "+f"((d)[2]), "+f"((d)[3]) \
        : "r"((a)[0]), "r"((a)[1]), "r"((a)[2]), "r"((a)[3]), "r"(b0), "r"(b1))

__device__ __forceinline__ uint32_t pack_h2(float a, float b) {
    __half2 h = __floats2half2_rn(a, b);
    return *(uint32_t*)&h;
}
__device__ __forceinline__ float ex2f(float x) {
    float y; asm("ex2.approx.ftz.f32 %0, %1;" : "=f"(y) : "f"(x)); return y;
}

// ---------------------------------------------------------------------------
// Kernel 1: QKV projection on tensor cores (fp16 hi/lo 3-term, fp32 accum).
// y = x @ W^T  ==  S = Q K^T pattern with A=x rows, B=W [out][in] rows.
// grid = (BATCH*SEQ/64, 3), 256 thr / 8 warps.
// warp w: rows 16*(w&3)..+15, cols 32*(w>>2)..+31.
// ---------------------------------------------------------------------------
__global__ __launch_bounds__(256) void qkv_proj_kernel(
    const float* __restrict__ x,  const float* __restrict__ Wk,
    const float* __restrict__ Wq, const float* __restrict__ Wv)
{
    __shared__ __align__(16) uint8_t smx[2][64 * 144];   // x hi, lo  (144B row pitch)
    __shared__ __align__(16) uint8_t smw[2][64 * 144];   // W hi, lo

    const int tid  = threadIdx.x;
    const int w    = tid >> 5;
    const int lane = tid & 31;
    const int row0 = blockIdx.x * 64;
    const int m    = blockIdx.y;

    const float* W = (m == 0) ? Wq : (m == 1) ? Wk : Wv;

    // ---- load + hi/lo convert x and W into smem (coalesced float4) ----
    for (int i = tid; i < 64 * 16; i += 256) {
        int r = i >> 4, c4 = (i & 15) << 2;
        float4 v = *(const float4*)&x[(size_t)(row0 + r) * HEAD + c4];
        __half h0 = __float2half_rn(v.x), h1 = __float2half_rn(v.y);
        __half h2 = __float2half_rn(v.z), h3 = __float2half_rn(v.w);
        uint32_t off = (uint32_t)r * 144 + (uint32_t)c4 * 2;
        *(uint32_t*)&smx[0][off]     = pack_h2(__half2float(h0) ? v.x : v.x, 0.f); // placeholder no
        // (replaced below)
        (void)off;
        // -- real packing --
        __half2 hh; hh.x = h0; hh.y = h1;
        *(uint32_t*)&smx[0][off]     = *(uint32_t*)&hh;
        hh.x = h2; hh.y = h3;
        *(uint32_t*)&smx[0][off + 4] = *(uint32_t*)&hh;
        __half l0 = __float2half_rn(v.x - __half2float(h0));
        __half l1 = __float2half_rn(v.y - __half2float(h1));
        __half l2 = __float2half_rn(v.z - __half2float(h2));
        __half l3 = __float2half_rn(v.w - __half2float(h3));
        hh.x = l0; hh.y = l1;
        *(uint32_t*)&smx[1][off]     = *(uint32_t*)&hh;
        hh.x = l2; hh.y = l3;
        *(uint32_t*)&smx[1][off + 4] = *(uint32_t*)&hh;
    }
    for (int i = tid; i < 64 * 16; i += 256) {
        int r = i >> 4, c4 = (i & 15) << 2;
        float4 v = *(const float4*)&W[(size_t)r * HEAD + c4];
        __half h0 = __float2half_rn(v.x), h1 = __float2half_rn(v.y);
        __half h2 = __float2half_rn(v.z), h3 = __float2half_rn(v.w);
        uint32_t off = (uint32_t)r * 144 + (uint32_t)c4 * 2;
        __half2 hh; hh.x = h0; hh.y = h1;
        *(uint32_t*)&smw[0][off]     = *(uint32_t*)&hh;
        hh.x = h2; hh.y = h3;
        *(uint32_t*)&smw[0][off + 4] = *(uint32_t*)&hh;
        __half l0 = __float2half_rn(v.x - __half2float(h0));
        __half l1 = __float2half_rn(v.y - __half2float(h1));
        __half l2 = __float2half_rn(v.z - __half2float(h2));
        __half l3 = __float2half_rn(v.w - __half2float(h3));
        hh.x = l0; hh.y = l1;
        *(uint32_t*)&smw[1][off]     = *(uint32_t*)&hh;
        hh.x = l2; hh.y = l3;
        *(uint32_t*)&smw[1][off + 4] = *(uint32_t*)&hh;
    }
    __syncthreads();

    // ---- A fragments: x hi/lo for this warp's 16 rows ----
    uint32_t xh[4][4], xl[4][4];
    {
        const uint32_t base = (uint32_t)(16 * (w & 3) + (lane & 15)) * 144 + ((uint32_t)(lane >> 4) << 4);
        const uint32_t rah = smem_u32(&smx[0][0]) + base;
        const uint32_t ral = smem_u32(&smx[1][0]) + base;
        #pragma unroll
        for (int ks = 0; ks < 4; ks++) {
            LDSM4(xh[ks], rah + ks * 32);
            LDSM4(xl[ks], ral + ks * 32);
        }
    }

    // ---- 3-term mma: s = xh*Wh + xh*Wl + xl*Wh ----
    float s[16];
    #pragma unroll
    for (int i = 0; i < 16; i++) s[i] = 0.f;

    #pragma unroll
    for (int ks = 0; ks < 4; ks++) {
        #pragma unroll
        for (int pr = 0; pr < 2; pr++) {
            const uint32_t a = smem_u32(&smw[0][0]) +
                (uint32_t)(32 * (w >> 2) + pr * 16 + (lane & 15)) * 144 +
                ((uint32_t)(lane >> 4) << 4) + ks * 32;
            uint32_t wh4[4], wl4[4];
            LDSM4(wh4, a);
            LDSM4(wl4, a + 9216);
            float* s0 = s + (2 * pr) * 4;
            float* s1 = s + (2 * pr + 1) * 4;
            MMA16816F16(s0, xh[ks], wh4[0], wh4[2]);
            MMA16816F16(s0, xh[ks], wl4[0], wl4[2]);
            MMA16816F16(s0, xl[ks], wh4[0], wh4[2]);
            MMA16816F16(s1, xh[ks], wh4[1], wh4[3]);
            MMA16816F16(s1, xh[ks], wl4[1], wl4[3]);
            MMA16816F16(s1, xl[ks], wh4[1], wh4[3]);
        }
    }

    // ---- epilogue: scale, convert fp16, store ----
    const int b    = row0 / SEQ;
    const int r0   = 16 * (w & 3) + (lane >> 2);
    const int g0   = row0 + r0;            // == b*SEQ + t0
    const int g1   = g0 + 8;
    const int tv0  = g0 - b * SEQ;
    const int tv1  = tv0 + 8;
    const float sc = (m == 0) ? SCALE_LOG2E : 1.0f;

    #pragma unroll
    for (int nt = 0; nt < 4; nt++) {
        const int col = 32 * (w >> 2) + nt * 8 + 2 * (lane & 3);
        float a0 = s[nt * 4]     * sc, a1 = s[nt * 4 + 1] * sc;
        float a2 = s[nt * 4 + 2] * sc, a3 = s[nt * 4 + 3] * sc;
        if (m < 2) {
            __half* dst = (m == 0) ? g_qh : g_kh;
            *(uint32_t*)&dst[(size_t)g0 * HEAD + col] = pack_h2(a0, a1);
            *(uint32_t*)&dst[(size_t)g1 * HEAD + col] = pack_h2(a2, a3);
        } else {
            g_vTh[((size_t)b * HEAD + col)     * SEQ + tv0] = __float2half_rn(a0);
            g_vTh[((size_t)b * HEAD + col + 1) * SEQ + tv0] = __float2half_rn(a1);
            g_vTh[((size_t)b * HEAD + col)     * SEQ + tv1] = __float2half_rn(a2);
            g_vTh[((size_t)b * HEAD + col + 1) * SEQ + tv1] = __float2half_rn(a3);
        }
    }
}

// ---------------------------------------------------------------------------
// Kernel 2: FA2-style fp16 mma.sync causal attention, double-buffered K/V,
// one __syncthreads per KV tile, LDG prefetch overlapped with compute.
// softmax via raw ex2 (q carries log2e). occ-2 (R5 regression proof).
// ---------------------------------------------------------------------------
__global__ __launch_bounds__(256, 2) void attn_kernel()
{
    __shared__ __align__(16) uint8_t sm[2 * 18432];

    const int tid  = threadIdx.x;
    const int w    = tid >> 5;
    const int lane = tid & 31;

    const int bx = blockIdx.x;
    const int b  = bx & 3;
    const int qt = (NQT - 1) - ((bx >> 2) & 31);  // heavy tiles first
    const int ch = bx >> 7;

    const int ntiles = 2 * qt + 2;
    const int t0 = ch * CHUNK;
    const int t1 = (t0 + CHUNK < ntiles) ? (t0 + CHUNK) : ntiles;
    if (t0 >= t1) return;

    const uint32_t smb = smem_u32(sm);
    uint8_t* smB = (uint8_t*)sm;

    // ---- stage Q in buf1 region [18432, 36864) and build A-fragments ----
    {
        const __half* qh = g_qh + ((size_t)b * SEQ + (size_t)qt * QROWS) * HEAD;
        for (int i = tid; i < 128 * 8; i += 256) {
            int r = i >> 3, c = i & 7;
            *(uint4*)(smB + 18432 + r * 144 + c * 16) = *(const uint4*)(qh + r * HEAD + c * 8);
        }
    }
    __syncthreads();

    uint32_t qF[4][4];
    {
        const uint32_t ra = smb + 18432 + (uint32_t)(w * 16 + (lane & 15)) * 144 + ((lane >> 4) << 4);
        #pragma unroll
        for (int ks = 0; ks < 4; ks++) LDSM4(qF[ks], ra + ks * 32);
    }

    const __half* kbase = g_kh  + (size_t)b * SEQ * HEAD;
    const __half* vbase = g_vTh + (size_t)b * HEAD * SEQ;

    const int e0r = tid >> 3,          e0c = tid & 7;
    const int e1r = (tid + 256) >> 3,  e1c = tid & 7;

    // ---- prologue: load tile t0 into buf0 (disjoint from Q's buf1) ----
    {
        const __half* kp = kbase + (size_t)t0 * KTILE * HEAD;
        const __half* vp = vbase + (size_t)t0 * KTILE;
        uint4 k0 = *(const uint4*)(kp + (size_t)e0r * HEAD + e0c * 8);
        uint4 k1 = *(const uint4*)(kp + (size_t)e1r * HEAD + e1c * 8);
        uint4 v0 = *(const uint4*)(vp + (size_t)e0r * SEQ  + e0c * 8);
        uint4 v1 = *(const uint4*)(vp + (size_t)e1r * SEQ  + e1c * 8);
        *(uint4*)(smB + e0r * 144 + e0c * 16)        = k0;
        *(uint4*)(smB + e1r * 144 + e1c * 16)        = k1;
        *(uint4*)(smB + 9216 + e0r * 144 + e0c * 16) = v0;
        *(uint4*)(smB + 9216 + e1r * 144 + e1c * 16) = v1;
    }

    float o[32];
    #pragma unroll
    for (int i = 0; i < 32; i++) o[i] = 0.f;
    float l0 = 0.f, l1 = 0.f;

    const int row_in0 = w * 16 + (lane >> 2);
    const int grow0 = qt * QROWS + row_in0;
    const int grow1 = grow0 + 8;
    const uint32_t lrow  = (uint32_t)(lane & 15) * 144;
    const uint32_t lhalf = ((uint32_t)(lane >> 4)) << 4;

    for (int tl = t0; tl < t1; tl++) {
        const uint32_t cur = (uint32_t)((tl - t0) & 1) * 18432;
        const uint32_t nxt = cur ^ 18432;

        __syncthreads();

        uint4 k0, k1, v0, v1;
        const bool have_next = (tl + 1 < t1);
        if (have_next) {
            const __half* kp = kbase + (size_t)(tl + 1) * KTILE * HEAD;
            const __half* vp = vbase + (size_t)(tl + 1) * KTILE;
            k0 = *(const uint4*)(kp + (size_t)e0r * HEAD + e0c * 8);
            k1 = *(const uint4*)(kp + (size_t)e1r * HEAD + e1c * 8);
            v0 = *(const uint4*)(vp + (size_t)e0r * SEQ  + e0c * 8);
            v1 = *(const uint4*)(vp + (size_t)e1r * SEQ  + e1c * 8);
        }

        // ---- S = Q K^T (fp16) ----
        float s[32];
        #pragma unroll
        for (int i = 0; i < 32; i++) s[i] = 0.f;

        #pragma unroll
        for (int ks = 0; ks < 4; ks++) {
            #pragma unroll
            for (int pr = 0; pr < 4; pr++) {
                const uint32_t a = smb + cur + (uint32_t)(pr * 16) * 144 + lrow + lhalf + ks * 32;
                uint32_t k4[4];
                LDSM4(k4, a);
                MMA16816F16(s + (2 * pr) * 4,     qF[ks], k4[0], k4[2]);
                MMA16816F16(s + (2 * pr + 1) * 4, qF[ks], k4[1], k4[3]);
            }
        }

        // ---- softmax via ex2 (S already carries log2e) ----
        const bool diag = (tl >= 2 * qt);
        uint32_t pF[4][4];
        #pragma unroll
        for (int nt = 0; nt < 8; nt++) {
            const float* sp = s + nt * 4;
            float p0, p1, p2, p3;
            if (diag) {
                const int colb = tl * KTILE + nt * 8 + 2 * (lane & 3);
                p0 = (colb     <= grow0) ? ex2f(sp[0]) : 0.f;
                p1 = (colb + 1 <= grow0) ? ex2f(sp[1]) : 0.f;
                p2 = (colb     <= grow1) ? ex2f(sp[2]) : 0.f;
                p3 = (colb + 1 <= grow1) ? ex2f(sp[3]) : 0.f;
            } else {
                p0 = ex2f(sp[0]); p1 = ex2f(sp[1]);
                p2 = ex2f(sp[2]); p3 = ex2f(sp[3]);
            }
            l0 += p0 + p1;
            l1 += p2 + p3;
            const int ks  = nt >> 1;
            const int sel = (nt & 1) << 1;
            pF[ks][sel]     = pack_h2(p0, p1);
            pF[ks][sel + 1] = pack_h2(p2, p3);
        }

        // ---- O += P V (fp16) ----
        #pragma unroll
        for (int ks = 0; ks < 4; ks++) {
            #pragma unroll
            for (int pr = 0; pr < 4; pr++) {
                const uint32_t a = smb + cur + 9216 + (uint32_t)(pr * 16) * 144 + lrow + lhalf + ks * 32;
                uint32_t v4[4];
                LDSM4(v4, a);
                MMA16816F16(o + (2 * pr) * 4,     pF[ks], v4[0], v4[2]);
                MMA16816F16(o + (2 * pr + 1) * 4, pF[ks], v4[1], v4[3]);
            }
        }

        if (have_next) {
            *(uint4*)(smB + nxt + e0r * 144 + e0c * 16)        = k0;
            *(uint4*)(smB + nxt + e1r * 144 + e1c * 16)        = k1;
            *(uint4*)(smB + nxt + 9216 + e0r * 144 + e0c * 16) = v0;
            *(uint4*)(smB + nxt + 9216 + e1r * 144 + e1c * 16) = v1;
        }
    }

    l0 += __shfl_xor_sync(0xffffffffu, l0, 1);
    l0 += __shfl_xor_sync(0xffffffffu, l0, 2);
    l1 += __shfl_xor_sync(0xffffffffu, l1, 1);
    l1 += __shfl_xor_sync(0xffffffffu, l1, 2);

    const size_t pb = ((size_t)(b * NQT + qt) * MAXCH + ch) * QROWS;
    const int c0 = 2 * (lane & 3);
    #pragma unroll
    for (int nt = 0; nt < 8; nt++) {
        float2 va = make_float2(o[nt * 4],     o[nt * 4 + 1]);
        float2 vb = make_float2(o[nt * 4 + 2], o[nt * 4 + 3]);
        *(float2*)&g_Opart[(pb + row_in0)     * HEAD + nt * 8 + c0] = va;
        *(float2*)&g_Opart[(pb + row_in0 + 8) * HEAD + nt * 8 + c0] = vb;
    }
    if ((lane & 3) == 0) {
        g_lpart[pb + row_in0]     = l0;
        g_lpart[pb + row_in0 + 8] = l1;
    }
}

// ---------------------------------------------------------------------------
// Kernel 3: combine split-KV partials (pure additive) + normalize.
// ---------------------------------------------------------------------------
__global__ __launch_bounds__(QROWS) void combine_kernel(float* __restrict__ out)
{
    const int b  = blockIdx.x & 3;
    const int qt = blockIdx.x >> 2;
    const int r  = threadIdx.x;
    const int nch = (2 * qt + 2 + CHUNK - 1) / CHUNK;

    float acc[HEAD];
    #pragma unroll
    for (int i = 0; i < HEAD; i++) acc[i] = 0.0f;
    float l = 0.0f;

    for (int ch = 0; ch < nch; ch++) {
        const size_t base = (((size_t)(b * NQT + qt) * MAXCH + ch) * QROWS + r) * HEAD;
        const float4* op = (const float4*)(g_Opart + base);
        #pragma unroll
        for (int i = 0; i < 16; i++) {
            float4 v = op[i];
            acc[4 * i] += v.x; acc[4 * i + 1] += v.y;
            acc[4 * i + 2] += v.z; acc[4 * i + 3] += v.w;
        }
        l += g_lpart[((size_t)(b * NQT + qt) * MAXCH + ch) * QROWS + r];
    }

    const float inv = 1.0f / l;
    float4* dst = (float4*)(out + ((size_t)b * SEQ + (size_t)qt * QROWS + r) * HEAD);
    #pragma unroll
    for (int i = 0; i < 16; i++) {
        dst[i] = make_float4(acc[4 * i] * inv, acc[4 * i + 1] * inv,
                             acc[4 * i + 2] * inv, acc[4 * i + 3] * inv);
    }
}

// ---------------------------------------------------------------------------
extern "C" void kernel_launch(void* const* d_in, const int* in_sizes, int n_in,
                              void* d_out, int out_size)
{
    const float* x  = (const float*)d_in[0];
    const float* Wk = (const float*)d_in[1];
    const float* Wq = (const float*)d_in[2];
    const float* Wv = (const float*)d_in[3];
    float* out = (float*)d_out;

    qkv_proj_kernel<<<dim3(BATCH * SEQ / 64, 3), 256>>>(x, Wk, Wq, Wv);
    attn_kernel<<<BATCH * NQT * MAXCH, 256>>>();
    combine_kernel<<<BATCH * NQT, QROWS>>>(out);
}